// round 2
// baseline (speedup 1.0000x reference)
#include <cuda_runtime.h>
#include <math.h>

#define NPTS   32768
#define NE     1024
#define EDIM   256
#define HW     1024
#define ZSIZE  8388608
#define OUT_ZQ   1
#define OUT_PERP (1 + ZSIZE)
#define OUT_IDX  (2 + ZSIZE)

#define WS_STRIDE 132
#define SMEM_BYTES ((EDIM * 64 + 32 * WS_STRIDE) * 4)

__device__ int   g_idx[NPTS];
__device__ float g_znorm[NPTS];
__device__ float g_enorm[NE];
__device__ float g_loss_sum;
__device__ int   g_counts[NE];

// ---------------------------------------------------------------------------
// znorm: sz_n = sequential fp32 sum of fl(z_k^2), ascending k (match XLA order)
// one thread per point; coalesced across hw
// ---------------------------------------------------------------------------
__global__ void znorm_kernel(const float* __restrict__ z) {
    int n = blockIdx.x * blockDim.x + threadIdx.x;
    int b = n >> 10, hw = n & 1023;
    const float* base = z + (size_t)b * (EDIM * HW) + hw;
    float s = 0.f;
#pragma unroll 8
    for (int c = 0; c < EDIM; c++) {
        float v = base[(size_t)c * HW];
        s = __fadd_rn(s, __fmul_rn(v, v));
    }
    g_znorm[n] = s;
}

// ---------------------------------------------------------------------------
// enorm: sw_c = sequential fp32 sum of fl(w_k^2), ascending k
// also zero counts / loss accumulator
// ---------------------------------------------------------------------------
__global__ void enorm_kernel(const float* __restrict__ w) {
    int c = blockIdx.x * blockDim.x + threadIdx.x;
    g_counts[c] = 0;
    if (c == 0) g_loss_sum = 0.f;
    const float* row = w + (size_t)c * EDIM;
    float s = 0.f;
#pragma unroll 8
    for (int k = 0; k < EDIM; k++) {
        float v = row[k];
        s = __fadd_rn(s, __fmul_rn(v, v));
    }
    g_enorm[c] = s;
}

// ---------------------------------------------------------------------------
// argmin: tiled GEMM (64 pts x 128 codes per CTA) with fused running argmin.
// Per-output dot is a pure ascending-k fp32 fma chain (matches fp32 GEMM).
// Final distance replicates reference association:
//   d = fl(fl(sz + sw) - fl(2*dot)), first-index tie-break.
// ---------------------------------------------------------------------------
__global__ __launch_bounds__(256, 2)
void argmin_kernel(const float* __restrict__ z, const float* __restrict__ w,
                   float* __restrict__ out) {
    extern __shared__ float smem[];
    float* z_s = smem;                 // [256][64], k-major
    float* w_s = smem + EDIM * 64;     // [32][WS_STRIDE], k-major

    int tid = threadIdx.x;
    int tx = tid & 15, ty = tid >> 4;
    int n0 = blockIdx.x * 64;
    int b = n0 >> 10, hw0 = n0 & 1023;
    const float* zb = z + (size_t)b * (EDIM * HW) + hw0;

    // load z tile (coalesced float4, conflict-free stores)
#pragma unroll
    for (int i = 0; i < 16; i++) {
        int e = tid + i * 256;
        int c = e >> 4, p4 = (e & 15) << 2;
        float4 v = *(const float4*)(zb + c * HW + p4);
        *(float4*)(z_s + c * 64 + p4) = v;
    }

    // per-thread point norms (4 points: n0 + ty*4 + i)
    float4 szv = *(const float4*)(g_znorm + n0 + ty * 4);
    float sz[4] = {szv.x, szv.y, szv.z, szv.w};

    float bmin[4] = {3.4e38f, 3.4e38f, 3.4e38f, 3.4e38f};
    int   bidx[4] = {0, 0, 0, 0};

    for (int ct = 0; ct < 8; ct++) {          // code tiles of 128
        int code0 = ct * 128;
        float acc[4][8];
#pragma unroll
        for (int i = 0; i < 4; i++)
#pragma unroll
            for (int j = 0; j < 8; j++) acc[i][j] = 0.f;

        for (int ks = 0; ks < 8; ks++) {      // K chunks of 32, ascending
            int k0 = ks * 32;
            __syncthreads();
            // load weight chunk: 128 codes x 32 k, transposed into smem
#pragma unroll
            for (int i = 0; i < 4; i++) {
                int e = tid + i * 256;
                int code = e >> 3, kk4 = (e & 7) << 2;
                float4 v = *(const float4*)(w + (size_t)(code0 + code) * EDIM + k0 + kk4);
                w_s[(kk4 + 0) * WS_STRIDE + code] = v.x;
                w_s[(kk4 + 1) * WS_STRIDE + code] = v.y;
                w_s[(kk4 + 2) * WS_STRIDE + code] = v.z;
                w_s[(kk4 + 3) * WS_STRIDE + code] = v.w;
            }
            __syncthreads();
#pragma unroll
            for (int kk = 0; kk < 32; kk++) {  // ascending k within chunk
                float4 zr = *(const float4*)(z_s + (k0 + kk) * 64 + ty * 4);
                float4 w0 = *(const float4*)(w_s + kk * WS_STRIDE + tx * 4);
                float4 w1 = *(const float4*)(w_s + kk * WS_STRIDE + 64 + tx * 4);
                float zv[4] = {zr.x, zr.y, zr.z, zr.w};
                float wv[8] = {w0.x, w0.y, w0.z, w0.w, w1.x, w1.y, w1.z, w1.w};
#pragma unroll
                for (int i = 0; i < 4; i++)
#pragma unroll
                    for (int j = 0; j < 8; j++)
                        acc[i][j] = fmaf(zv[i], wv[j], acc[i][j]);
            }
        }

        // replicate reference rounding and update running argmin
#pragma unroll
        for (int j = 0; j < 8; j++) {
            int code = code0 + ((j < 4) ? (tx * 4 + j) : (64 + tx * 4 + (j - 4)));
            float sw = __ldg(&g_enorm[code]);
#pragma unroll
            for (int i = 0; i < 4; i++) {
                float t1 = __fadd_rn(sz[i], sw);
                float t2 = __fmul_rn(2.0f, acc[i][j]);
                float d  = __fsub_rn(t1, t2);
                if (d < bmin[i]) { bmin[i] = d; bidx[i] = code; }
            }
        }
    }

    // reduce argmin across the 16 tx lanes (first-index tie break)
#pragma unroll
    for (int i = 0; i < 4; i++) {
        float v = bmin[i];
        int ix = bidx[i];
#pragma unroll
        for (int off = 8; off; off >>= 1) {
            float ov = __shfl_down_sync(0xffffffffu, v, off, 16);
            int   oi = __shfl_down_sync(0xffffffffu, ix, off, 16);
            if (ov < v || (ov == v && oi < ix)) { v = ov; ix = oi; }
        }
        if (tx == 0) {
            int n = n0 + ty * 4 + i;
            g_idx[n] = ix;
            out[OUT_IDX + n] = (float)ix;
            atomicAdd(&g_counts[ix], 1);
        }
    }
}

// ---------------------------------------------------------------------------
// gather: z_q_out = fl(z + fl(q - z)) (straight-through estimator, exact
// replication), plus loss sum accumulation
// ---------------------------------------------------------------------------
__global__ void gather_kernel(const float* __restrict__ z, const float* __restrict__ w,
                              float* __restrict__ out) {
    int gid = blockIdx.x * blockDim.x + threadIdx.x;   // one float4 each
    int o4 = gid << 2;
    int hw = o4 & 1023;
    int bc = o4 >> 10;
    int c = bc & 255, b = bc >> 8;
    int nb = (b << 10) + hw;

    int4 id = *(const int4*)(g_idx + nb);
    float4 zv = *(const float4*)(z + o4);
    float q0 = w[(size_t)id.x * EDIM + c];
    float q1 = w[(size_t)id.y * EDIM + c];
    float q2 = w[(size_t)id.z * EDIM + c];
    float q3 = w[(size_t)id.w * EDIM + c];

    float d0 = __fsub_rn(q0, zv.x), d1 = __fsub_rn(q1, zv.y);
    float d2 = __fsub_rn(q2, zv.z), d3 = __fsub_rn(q3, zv.w);

    float4 o;
    o.x = __fadd_rn(zv.x, d0);
    o.y = __fadd_rn(zv.y, d1);
    o.z = __fadd_rn(zv.z, d2);
    o.w = __fadd_rn(zv.w, d3);
    // out+OUT_ZQ is only 4B aligned (offset 1 float) -> scalar stores
    float* zq = out + OUT_ZQ + o4;
    zq[0] = o.x; zq[1] = o.y; zq[2] = o.z; zq[3] = o.w;

    float s = d0 * d0 + d1 * d1 + d2 * d2 + d3 * d3;

    // block reduction for loss
#pragma unroll
    for (int off = 16; off; off >>= 1) s += __shfl_down_sync(0xffffffffu, s, off);
    __shared__ float red[8];
    int lane = threadIdx.x & 31, wid = threadIdx.x >> 5;
    if (lane == 0) red[wid] = s;
    __syncthreads();
    if (wid == 0) {
        float t = (lane < 8) ? red[lane] : 0.f;
#pragma unroll
        for (int off = 4; off; off >>= 1) t += __shfl_down_sync(0xffffffffu, t, off);
        if (lane == 0) atomicAdd(&g_loss_sum, t);
    }
}

// ---------------------------------------------------------------------------
// finalize: perplexity from counts, loss from accumulated sumsq
// ---------------------------------------------------------------------------
__global__ void finalize_kernel(float* __restrict__ out) {
    int t = threadIdx.x;
    float em = (float)g_counts[t] * (1.0f / 32768.f);
    float s = em * logf(em + 1e-10f);
#pragma unroll
    for (int off = 16; off; off >>= 1) s += __shfl_down_sync(0xffffffffu, s, off);
    __shared__ float red[32];
    int lane = t & 31, wid = t >> 5;
    if (lane == 0) red[wid] = s;
    __syncthreads();
    if (wid == 0) {
        float v = red[lane];
#pragma unroll
        for (int off = 16; off; off >>= 1) v += __shfl_down_sync(0xffffffffu, v, off);
        if (lane == 0) {
            out[0] = g_loss_sum * (1.25f / 8388608.f);
            out[OUT_PERP] = expf(-v);
        }
    }
}

// ---------------------------------------------------------------------------
extern "C" void kernel_launch(void* const* d_in, const int* in_sizes, int n_in,
                              void* d_out, int out_size) {
    const float* z = (const float*)d_in[0];
    const float* w = (const float*)d_in[1];
    float* out = (float*)d_out;

    cudaFuncSetAttribute(argmin_kernel, cudaFuncAttributeMaxDynamicSharedMemorySize,
                         SMEM_BYTES);

    znorm_kernel<<<NPTS / 256, 256>>>(z);
    enorm_kernel<<<4, 256>>>(w);
    argmin_kernel<<<NPTS / 64, 256, SMEM_BYTES>>>(z, w, out);
    gather_kernel<<<ZSIZE / 4 / 256, 256>>>(z, w, out);
    finalize_kernel<<<1, 1024>>>(out);
}

// round 4
// speedup vs baseline: 1.4407x; 1.4407x over previous
#include <cuda_runtime.h>
#include <math.h>
#include <stdint.h>

#define NPTS   32768
#define NE     1024
#define EDIM   256
#define ZSIZE  8388608
#define OUT_ZQ   1
#define OUT_PERP (1 + ZSIZE)
#define OUT_IDX  (2 + ZSIZE)
#define MARGIN   2.5e-3f

__device__ float g_zt[NPTS * EDIM];               // 32MB transposed z
__device__ float g_scores[(size_t)NPTS * NE];     // 128MB approx scores
__device__ float g_min[NPTS];
__device__ int   g_idx[NPTS];
__device__ float g_enorm[NE];
__device__ int   g_counts[NE];
__device__ float g_loss_sum;

__device__ __forceinline__ uint32_t f2tf(float v) {
    uint32_t r; asm("cvt.rna.tf32.f32 %0, %1;" : "=r"(r) : "f"(v)); return r;
}
__device__ __forceinline__ float tfv(float v) { return __uint_as_float(f2tf(v)); }

#define MMA_TF32(d, a, b) \
    asm volatile("mma.sync.aligned.m16n8k8.row.col.f32.tf32.tf32.f32 " \
        "{%0,%1,%2,%3}, {%4,%5,%6,%7}, {%8,%9}, {%0,%1,%2,%3};" \
        : "+f"((d)[0]), "+f"((d)[1]), "+f"((d)[2]), "+f"((d)[3]) \
        : "r"((a)[0]), "r"((a)[1]), "r"((a)[2]), "r"((a)[3]), \
          "r"((b)[0]), "r"((b)[1]))

// ======================= transpose: z (B,C,H,W) -> z_t (N, C) =======================
__global__ __launch_bounds__(256) void transpose_kernel(const float* __restrict__ z) {
    __shared__ float tile[256 * 33];
    int t = threadIdx.x;
    int n0 = blockIdx.x * 32;
    int b = n0 >> 10, hw0 = n0 & 1023;
    const float* zb = z + (size_t)b * 262144 + hw0;
#pragma unroll
    for (int i = 0; i < 8; i++) {
        int idx = t + i * 256;
        int c = idx >> 3, q = idx & 7;
        float4 v = *(const float4*)(zb + (size_t)c * 1024 + q * 4);
        tile[c * 33 + q * 4 + 0] = v.x; tile[c * 33 + q * 4 + 1] = v.y;
        tile[c * 33 + q * 4 + 2] = v.z; tile[c * 33 + q * 4 + 3] = v.w;
    }
    __syncthreads();
#pragma unroll
    for (int i = 0; i < 8; i++) {
        int idx = t + i * 256;
        int m = idx >> 6, c4 = idx & 63;
        float4 o;
        o.x = tile[(c4 * 4 + 0) * 33 + m]; o.y = tile[(c4 * 4 + 1) * 33 + m];
        o.z = tile[(c4 * 4 + 2) * 33 + m]; o.w = tile[(c4 * 4 + 3) * 33 + m];
        *(float4*)(g_zt + (size_t)(n0 + m) * 256 + c4 * 4) = o;
    }
}

// ======================= enorm: exact ||e||^2 + zero accumulators =======================
__global__ void enorm_kernel(const float* __restrict__ w) {
    int c = blockIdx.x * blockDim.x + threadIdx.x;
    g_counts[c] = 0;
    if (c == 0) g_loss_sum = 0.f;
    const float* row = w + (size_t)c * EDIM;
    float s = 0.f;
#pragma unroll 8
    for (int k = 0; k < EDIM; k++) {
        float v = row[k];
        s = __fadd_rn(s, __fmul_rn(v, v));
    }
    g_enorm[c] = s;
}

// ======================= HMMA tf32: approx scores + per-point min =======================
// CTA: 128 points x 1024 codes (j-loop over 8 tiles of 128 codes).
// A (128x256 tf32) smem-resident, stride 260. B double-buffered 128x32 chunks,
// stride 36. 8 warps in 2(M) x 4(N); per warp 4x4 m16n8 frags, K-steps of 8.
#define AST 260
#define BST 36
#define A_ELEMS (128 * AST)            // 33280 floats
#define B_ELEMS (128 * BST)            // 4608 floats
#define SMEM_MMA ((A_ELEMS + 2 * B_ELEMS + NE + 512) * 4)   // 176128 B

__global__ __launch_bounds__(256, 1)
void mma_kernel(const float* __restrict__ w) {
    extern __shared__ float sm[];
    float* A_s  = sm;
    float* B_s  = sm + A_ELEMS;        // [2][B_ELEMS]
    float* sw_s = B_s + 2 * B_ELEMS;   // [1024]
    float* smin = sw_s + NE;           // [4][128]

    int tid = threadIdx.x;
    int lane = tid & 31, wid = tid >> 5;
    int g = lane >> 2, t = lane & 3;
    int wm = wid >> 2, wn = wid & 3;
    int n0 = blockIdx.x * 128;

    for (int i = tid; i < NE; i += 256) sw_s[i] = g_enorm[i];
    for (int i = tid; i < 512; i += 256) smin[i] = 3.4e38f;

    // A fill: 128 points x 256 dims, cvt to tf32
#pragma unroll
    for (int i = 0; i < 32; i++) {
        int idx = tid + i * 256;
        int m = idx >> 6, kq = idx & 63;
        float4 v = *(const float4*)(g_zt + (size_t)(n0 + m) * 256 + kq * 4);
        float4 o = make_float4(tfv(v.x), tfv(v.y), tfv(v.z), tfv(v.w));
        *(float4*)(A_s + m * AST + kq * 4) = o;
    }

    float rmin[8];
#pragma unroll
    for (int r = 0; r < 8; r++) rmin[r] = 3.4e38f;

    for (int j = 0; j < 8; j++) {
        float acc[4][4][4];
#pragma unroll
        for (int mt = 0; mt < 4; mt++)
#pragma unroll
            for (int nt = 0; nt < 4; nt++)
#pragma unroll
                for (int q = 0; q < 4; q++) acc[mt][nt][q] = 0.f;

        // prologue: B chunk kc=0 into buf 0
        {
            const float* wp = w + (size_t)(j * 128) * 256;
#pragma unroll
            for (int i = 0; i < 4; i++) {
                int idx = tid + i * 256;
                int c = idx >> 3, kq = idx & 7;
                float4 v = *(const float4*)(wp + (size_t)c * 256 + kq * 4);
                float4 o = make_float4(tfv(v.x), tfv(v.y), tfv(v.z), tfv(v.w));
                *(float4*)(B_s + c * BST + kq * 4) = o;
            }
        }
        __syncthreads();

        for (int kc = 0; kc < 8; kc++) {
            int buf = kc & 1;
            if (kc < 7) {
                const float* wp = w + (size_t)(j * 128) * 256 + (kc + 1) * 32;
#pragma unroll
                for (int i = 0; i < 4; i++) {
                    int idx = tid + i * 256;
                    int c = idx >> 3, kq = idx & 7;
                    float4 v = *(const float4*)(wp + (size_t)c * 256 + kq * 4);
                    float4 o = make_float4(tfv(v.x), tfv(v.y), tfv(v.z), tfv(v.w));
                    *(float4*)(B_s + (buf ^ 1) * B_ELEMS + c * BST + kq * 4) = o;
                }
            }
            const float* Bb = B_s + buf * B_ELEMS;
#pragma unroll
            for (int ks = 0; ks < 4; ks++) {
                int k0 = kc * 32 + ks * 8;
                uint32_t bf[4][2];
#pragma unroll
                for (int nt = 0; nt < 4; nt++) {
                    int code = wn * 32 + nt * 8 + g;
                    bf[nt][0] = __float_as_uint(Bb[code * BST + ks * 8 + t]);
                    bf[nt][1] = __float_as_uint(Bb[code * BST + ks * 8 + t + 4]);
                }
#pragma unroll
                for (int mt = 0; mt < 4; mt++) {
                    int row = wm * 64 + mt * 16 + g;
                    uint32_t af[4];
                    af[0] = __float_as_uint(A_s[row * AST + k0 + t]);
                    af[1] = __float_as_uint(A_s[(row + 8) * AST + k0 + t]);
                    af[2] = __float_as_uint(A_s[row * AST + k0 + t + 4]);
                    af[3] = __float_as_uint(A_s[(row + 8) * AST + k0 + t + 4]);
#pragma unroll
                    for (int nt = 0; nt < 4; nt++)
                        MMA_TF32(acc[mt][nt], af, bf[nt]);
                }
            }
            __syncthreads();
        }

        // epilogue: s = sw - 2*dot, store + running min
#pragma unroll
        for (int nt = 0; nt < 4; nt++) {
            int colg = j * 128 + wn * 32 + nt * 8 + 2 * t;
            float sw0 = sw_s[colg], sw1 = sw_s[colg + 1];
#pragma unroll
            for (int mt = 0; mt < 4; mt++) {
                int row0 = wm * 64 + mt * 16 + g;
                float s00 = fmaf(-2.f, acc[mt][nt][0], sw0);
                float s01 = fmaf(-2.f, acc[mt][nt][1], sw1);
                float s10 = fmaf(-2.f, acc[mt][nt][2], sw0);
                float s11 = fmaf(-2.f, acc[mt][nt][3], sw1);
                *(float2*)(g_scores + (size_t)(n0 + row0) * 1024 + colg) = make_float2(s00, s01);
                *(float2*)(g_scores + (size_t)(n0 + row0 + 8) * 1024 + colg) = make_float2(s10, s11);
                rmin[mt * 2]     = fminf(rmin[mt * 2],     fminf(s00, s01));
                rmin[mt * 2 + 1] = fminf(rmin[mt * 2 + 1], fminf(s10, s11));
            }
        }
    }

    // min across the 4 tig lanes of each group, then across wn warps
#pragma unroll
    for (int r = 0; r < 8; r++) {
        float v = rmin[r];
        v = fminf(v, __shfl_xor_sync(0xffffffffu, v, 1));
        v = fminf(v, __shfl_xor_sync(0xffffffffu, v, 2));
        if (t == 0) {
            int row = wm * 64 + (r >> 1) * 16 + (r & 1) * 8 + g;
            smin[wn * 128 + row] = v;
        }
    }
    __syncthreads();
    if (tid < 128) {
        float v = fminf(fminf(smin[tid], smin[128 + tid]),
                        fminf(smin[256 + tid], smin[384 + tid]));
        g_min[n0 + tid] = v;
    }
}

// ======================= rescore: exact argmin over candidates =======================
__global__ __launch_bounds__(256) void rescore_kernel(const float* __restrict__ w,
                                                      float* __restrict__ out) {
    __shared__ float z_s[32 * 256];
    __shared__ int cand[8][128];
    __shared__ int ccnt[8];
    int t = threadIdx.x, wrp = t >> 5, lane = t & 31;
    int n0 = blockIdx.x * 32;

#pragma unroll
    for (int i = 0; i < 8; i++) {
        int idx = t + i * 256;
        int p = idx >> 6, q = idx & 63;
        ((float4*)z_s)[idx] = *(const float4*)(g_zt + (size_t)(n0 + p) * 256 + q * 4);
    }
    __syncthreads();

    for (int pi = 0; pi < 4; pi++) {
        int p = wrp * 4 + pi;
        int n = n0 + p;
        float thr = g_min[n] + MARGIN;
        if (lane == 0) ccnt[wrp] = 0;
        __syncwarp();
        const float4* sp = (const float4*)(g_scores + (size_t)n * 1024);
#pragma unroll
        for (int g = 0; g < 8; g++) {
            float4 s4 = sp[g * 32 + lane];
            int cb = (g * 32 + lane) * 4;
            if (s4.x <= thr) { int ps = atomicAdd(&ccnt[wrp], 1); if (ps < 128) cand[wrp][ps] = cb + 0; }
            if (s4.y <= thr) { int ps = atomicAdd(&ccnt[wrp], 1); if (ps < 128) cand[wrp][ps] = cb + 1; }
            if (s4.z <= thr) { int ps = atomicAdd(&ccnt[wrp], 1); if (ps < 128) cand[wrp][ps] = cb + 2; }
            if (s4.w <= thr) { int ps = atomicAdd(&ccnt[wrp], 1); if (ps < 128) cand[wrp][ps] = cb + 3; }
        }
        __syncwarp();
        int cnt = ccnt[wrp]; if (cnt > 128) cnt = 128;

        float bd = 3.4e38f; int bc = 0x7fffffff;
        const float* zr = z_s + p * 256;
        for (int bse = 0; bse < cnt; bse += 31) {
            int my = bse + lane;
            bool act = (lane < 31) && (my < cnt);
            int code = cand[wrp][act ? my : 0];
            const float* wr = w + (size_t)code * EDIM;
            float dot = 0.f, szl = 0.f;
#pragma unroll 8
            for (int k = 0; k < 256; k++) {
                float v = zr[k];                        // broadcast
                dot = fmaf(v, wr[k], dot);              // exact ascending chain
                szl = __fadd_rn(szl, __fmul_rn(v, v));  // exact ||z||^2 chain
            }
            float swc = __ldg(&g_enorm[code]);
            float d = __fsub_rn(__fadd_rn(szl, swc), __fmul_rn(2.f, dot));
            if (act && (d < bd || (d == bd && code < bc))) { bd = d; bc = code; }
        }
#pragma unroll
        for (int off = 16; off; off >>= 1) {
            float od = __shfl_xor_sync(0xffffffffu, bd, off);
            int   oc = __shfl_xor_sync(0xffffffffu, bc, off);
            if (od < bd || (od == bd && oc < bc)) { bd = od; bc = oc; }
        }
        if (lane == 0) {
            g_idx[n] = bc;
            out[OUT_IDX + n] = (float)bc;
            atomicAdd(&g_counts[bc], 1);
        }
    }
}

// ======================= gather: z_q_out (STE) + loss =======================
__global__ __launch_bounds__(256) void gather_kernel(const float* __restrict__ z,
                                                     const float* __restrict__ w,
                                                     float* __restrict__ out) {
    __shared__ float wrow[32][257];
    __shared__ int ids[32];
    __shared__ float red[8];
    int t = threadIdx.x, lane = t & 31, wrp = t >> 5;
    int n0 = blockIdx.x * 32;
    int b = n0 >> 10, hw0 = n0 & 1023;

    if (t < 32) ids[t] = g_idx[n0 + t];
    __syncthreads();
#pragma unroll
    for (int i = 0; i < 8; i++) {
        int idx = t + i * 256;
        int r = idx >> 6, q = idx & 63;
        float4 v = *(const float4*)(w + (size_t)ids[r] * 256 + q * 4);
        wrow[r][q * 4 + 0] = v.x; wrow[r][q * 4 + 1] = v.y;
        wrow[r][q * 4 + 2] = v.z; wrow[r][q * 4 + 3] = v.w;
    }
    __syncthreads();

    float loss = 0.f;
    const float* zb = z + (size_t)b * 262144 + hw0;
    float* ob = out + OUT_ZQ + (size_t)b * 262144 + hw0;
    for (int c = wrp; c < 256; c += 8) {
        float zv = zb[(size_t)c * 1024 + lane];
        float q = wrow[lane][c];
        float d = __fsub_rn(q, zv);
        ob[(size_t)c * 1024 + lane] = __fadd_rn(zv, d);
        loss += d * d;
    }
#pragma unroll
    for (int off = 16; off; off >>= 1) loss += __shfl_down_sync(0xffffffffu, loss, off);
    if (lane == 0) red[wrp] = loss;
    __syncthreads();
    if (wrp == 0) {
        float v = (lane < 8) ? red[lane] : 0.f;
#pragma unroll
        for (int off = 4; off; off >>= 1) v += __shfl_down_sync(0xffffffffu, v, off);
        if (lane == 0) atomicAdd(&g_loss_sum, v);
    }
}

// ======================= finalize =======================
__global__ void finalize_kernel(float* __restrict__ out) {
    int t = threadIdx.x;
    float em = (float)g_counts[t] * (1.0f / 32768.f);
    float s = em * logf(em + 1e-10f);
#pragma unroll
    for (int off = 16; off; off >>= 1) s += __shfl_down_sync(0xffffffffu, s, off);
    __shared__ float red[32];
    int lane = t & 31, wid = t >> 5;
    if (lane == 0) red[wid] = s;
    __syncthreads();
    if (wid == 0) {
        float v = red[lane];
#pragma unroll
        for (int off = 16; off; off >>= 1) v += __shfl_down_sync(0xffffffffu, v, off);
        if (lane == 0) {
            out[0] = g_loss_sum * (1.25f / 8388608.f);
            out[OUT_PERP] = expf(-v);
        }
    }
}

// ======================= launch =======================
extern "C" void kernel_launch(void* const* d_in, const int* in_sizes, int n_in,
                              void* d_out, int out_size) {
    const float* z = (const float*)d_in[0];
    const float* w = (const float*)d_in[1];
    float* out = (float*)d_out;

    cudaFuncSetAttribute(mma_kernel, cudaFuncAttributeMaxDynamicSharedMemorySize, SMEM_MMA);

    transpose_kernel<<<NPTS / 32, 256>>>(z);
    enorm_kernel<<<4, 256>>>(w);
    mma_kernel<<<NPTS / 128, 256, SMEM_MMA>>>(w);
    rescore_kernel<<<NPTS / 32, 256>>>(w, out);
    gather_kernel<<<NPTS / 32, 256>>>(z, w, out);
    finalize_kernel<<<1, 1024>>>(out);
}